// round 4
// baseline (speedup 1.0000x reference)
#include <cuda_runtime.h>
#include <cuda_bf16.h>
#include <cstdint>

// Problem constants
#define B_   64
#define NN_  64
#define HL_  50
#define IN_  384
#define POS_ 64
#define ATT_ 256
#define NEWS_ 448          // IN_ + POS_
#define W1STRIDE 896       // 2*NEWS_

// Scratch (no allocations allowed -> device globals)
__device__ float g_pn [B_ * NN_ * ATT_];   // 4096 x 256
__device__ float g_plb[B_ * HL_ * ATT_];   // 3200 x 256  (pl + P2 + b1)
__device__ float g_P2 [HL_ * ATT_];        // 50 x 256    (pos part of pl + b1)

// ---------------------------------------------------------------------------
// P2[h,a] = b1[a] + sum_d pos_emb[1+h, d] * W1[a, 832+d]
// ---------------------------------------------------------------------------
__global__ void p2_kernel(const float* __restrict__ pos_emb,
                          const float* __restrict__ W1,
                          const float* __restrict__ b1,
                          float* __restrict__ P2) {
    int h = blockIdx.x;          // 0..49
    int a = threadIdx.x;         // 0..255
    __shared__ float ps[POS_];
    if (a < POS_) ps[a] = pos_emb[(1 + h) * POS_ + a];
    __syncthreads();
    float s = b1[a];
    const float* wrow = W1 + a * W1STRIDE + 832;   // 448 + 384
    #pragma unroll
    for (int d = 0; d < POS_; d++) s += ps[d] * wrow[d];
    P2[h * ATT_ + a] = s;
}

// ---------------------------------------------------------------------------
// C[m, n] = sum_{k<384} A[m,k] * W1[n, wOff+k]  (+ P2[(m%50), n] if addP2)
// A: M x 384 row-major, W1: 256 x 896 row-major. Tiles 64x64x16, 256 thr.
// ---------------------------------------------------------------------------
__global__ void gemm_wt_kernel(const float* __restrict__ A,
                               const float* __restrict__ W1,
                               int wOff,
                               const float* __restrict__ P2,   // may be null
                               float* __restrict__ C) {
    __shared__ float As[16][68];
    __shared__ float Bs[16][68];
    const int m0 = blockIdx.y * 64;
    const int n0 = blockIdx.x * 64;
    const int tid = threadIdx.x;
    const int tx = tid & 15, ty = tid >> 4;       // 16 x 16 compute map
    const int lr = tid >> 2, lc = tid & 3;        // 64 rows x 4 quads load map

    float acc[4][4] = {};

    for (int k0 = 0; k0 < IN_; k0 += 16) {
        float4 av = *(const float4*)&A [(m0 + lr) * IN_      + k0 + lc * 4];
        float4 bv = *(const float4*)&W1[(n0 + lr) * W1STRIDE + wOff + k0 + lc * 4];
        As[lc*4+0][lr] = av.x; As[lc*4+1][lr] = av.y;
        As[lc*4+2][lr] = av.z; As[lc*4+3][lr] = av.w;
        Bs[lc*4+0][lr] = bv.x; Bs[lc*4+1][lr] = bv.y;
        Bs[lc*4+2][lr] = bv.z; Bs[lc*4+3][lr] = bv.w;
        __syncthreads();
        #pragma unroll
        for (int kk = 0; kk < 16; kk++) {
            float4 a4 = *(const float4*)&As[kk][ty * 4];
            float4 b4 = *(const float4*)&Bs[kk][tx * 4];
            float ar[4] = {a4.x, a4.y, a4.z, a4.w};
            float br[4] = {b4.x, b4.y, b4.z, b4.w};
            #pragma unroll
            for (int i = 0; i < 4; i++)
                #pragma unroll
                for (int j = 0; j < 4; j++)
                    acc[i][j] = fmaf(ar[i], br[j], acc[i][j]);
        }
        __syncthreads();
    }

    #pragma unroll
    for (int i = 0; i < 4; i++) {
        int m = m0 + ty * 4 + i;
        #pragma unroll
        for (int j = 0; j < 4; j++) {
            int n = n0 + tx * 4 + j;
            float v = acc[i][j];
            if (P2) v += P2[(m % HL_) * ATT_ + n];
            C[m * ATT_ + n] = v;
        }
    }
}

// ---------------------------------------------------------------------------
// nf output: [news_vec | zeros]  -> out_nf (4096 x 448)
// ---------------------------------------------------------------------------
__global__ void nf_kernel(const float* __restrict__ news, float* __restrict__ out_nf) {
    int idx = blockIdx.x * blockDim.x + threadIdx.x;
    if (idx >= B_ * NN_ * NEWS_) return;
    int d = idx % NEWS_;
    int r = idx / NEWS_;
    out_nf[idx] = (d < IN_) ? news[r * IN_ + d] : 0.0f;
}

// ---------------------------------------------------------------------------
// Fused attention: per block = (b, 4 consecutive n).
//   logits[j,h] = sum_a tanh(pn[b,n0+j,a] + plb[b,h,a]) * W2[a]
//   masked softmax over h, then out = attn @ [log_vec | pos_emb]
// ---------------------------------------------------------------------------
#define NPB 4
__device__ __forceinline__ float tanh_approx(float x) {
    float y;
    asm("tanh.approx.f32 %0, %1;" : "=f"(y) : "f"(x));
    return y;
}

__global__ void attn_kernel(const float* __restrict__ pn,
                            const float* __restrict__ plb,
                            const float* __restrict__ log_vec,
                            const float* __restrict__ pos_emb,
                            const int*   __restrict__ log_mask,
                            const float* __restrict__ W2,
                            float* __restrict__ out_u) {
    extern __shared__ float sm[];
    float* plb_s   = sm;                   // 50*256 = 12800
    float* logits_s = sm + HL_ * ATT_;     // NPB*64
    float* attn_s   = logits_s + NPB * 64; // NPB*64
    __shared__ int mask_s[HL_];

    const int b  = blockIdx.y;
    const int n0 = blockIdx.x * NPB;
    const int tid = threadIdx.x;
    const int lane = tid & 31, w = tid >> 5;

    // stage plb[b] (50x256) into smem, vectorized
    {
        const float4* src = (const float4*)(plb + b * HL_ * ATT_);
        float4* dst = (float4*)plb_s;
        for (int i = tid; i < HL_ * ATT_ / 4; i += 256) dst[i] = src[i];
    }
    if (tid < HL_) mask_s[tid] = log_mask[b * HL_ + tid];

    // per-thread registers: pn rows + W2, a = lane + 32*j8
    float pnr[NPB][8], w2r[8];
    #pragma unroll
    for (int j8 = 0; j8 < 8; j8++) {
        int a = lane + 32 * j8;
        w2r[j8] = W2[a];
        #pragma unroll
        for (int j = 0; j < NPB; j++)
            pnr[j][j8] = pn[(b * NN_ + n0 + j) * ATT_ + a];
    }
    __syncthreads();

    // main loop: warp w handles h = w, w+8, ...
    for (int h = w; h < HL_; h += 8) {
        float acc[NPB] = {0.f, 0.f, 0.f, 0.f};
        #pragma unroll
        for (int j8 = 0; j8 < 8; j8++) {
            float pl = plb_s[h * ATT_ + lane + 32 * j8];
            #pragma unroll
            for (int j = 0; j < NPB; j++) {
                float t = tanh_approx(pl + pnr[j][j8]);
                acc[j] = fmaf(t, w2r[j8], acc[j]);
            }
        }
        #pragma unroll
        for (int j = 0; j < NPB; j++) {
            float v = acc[j];
            v += __shfl_xor_sync(0xffffffffu, v, 16);
            v += __shfl_xor_sync(0xffffffffu, v, 8);
            v += __shfl_xor_sync(0xffffffffu, v, 4);
            v += __shfl_xor_sync(0xffffffffu, v, 2);
            v += __shfl_xor_sync(0xffffffffu, v, 1);
            if (lane == 0) logits_s[j * 64 + h] = v;
        }
    }
    __syncthreads();

    // masked softmax: warp j (< NPB) handles row j
    if (w < NPB) {
        const int j = w;
        int h0 = lane, h1 = lane + 32;
        float v0 = -3e38f, v1 = -3e38f;
        if (h0 < HL_) v0 = (mask_s[h0] == 0) ? -1e9f : logits_s[j * 64 + h0];
        if (h1 < HL_) v1 = (mask_s[h1] == 0) ? -1e9f : logits_s[j * 64 + h1];
        float m = fmaxf(v0, v1);
        #pragma unroll
        for (int s = 16; s; s >>= 1) m = fmaxf(m, __shfl_xor_sync(0xffffffffu, m, s));
        float e0 = (h0 < HL_) ? __expf(v0 - m) : 0.f;
        float e1 = (h1 < HL_) ? __expf(v1 - m) : 0.f;
        float ssum = e0 + e1;
        #pragma unroll
        for (int s = 16; s; s >>= 1) ssum += __shfl_xor_sync(0xffffffffu, ssum, s);
        float inv = 1.f / ssum;
        if (h0 < HL_) attn_s[j * 64 + h0] = e0 * inv;
        if (h1 < HL_) attn_s[j * 64 + h1] = e1 * inv;
    }
    __syncthreads();

    // epilogue: out[b, n0+j, d] = sum_h attn[j,h] * lf[b,h,d]
    for (int d = tid; d < NEWS_; d += 256) {
        float acc[NPB] = {0.f, 0.f, 0.f, 0.f};
        if (d < IN_) {
            for (int h = 0; h < HL_; h++) {
                float lv = log_vec[(b * HL_ + h) * IN_ + d];
                #pragma unroll
                for (int j = 0; j < NPB; j++)
                    acc[j] = fmaf(attn_s[j * 64 + h], lv, acc[j]);
            }
        } else {
            int dp = d - IN_;
            for (int h = 0; h < HL_; h++) {
                float lv = pos_emb[(1 + h) * POS_ + dp];
                #pragma unroll
                for (int j = 0; j < NPB; j++)
                    acc[j] = fmaf(attn_s[j * 64 + h], lv, acc[j]);
            }
        }
        #pragma unroll
        for (int j = 0; j < NPB; j++)
            out_u[(b * NN_ + n0 + j) * NEWS_ + d] = acc[j];
    }
}

// ---------------------------------------------------------------------------
extern "C" void kernel_launch(void* const* d_in, const int* in_sizes, int n_in,
                              void* d_out, int out_size) {
    const float* log_vec  = (const float*)d_in[0];   // (64,50,384)
    const int*   log_mask = (const int*)  d_in[1];   // (64,50)
    const float* news_vec = (const float*)d_in[2];   // (64,64,384)
    const float* pos_emb  = (const float*)d_in[3];   // (100,64)
    const float* W1       = (const float*)d_in[4];   // (256,896)
    const float* b1       = (const float*)d_in[5];   // (256)
    const float* W2       = (const float*)d_in[6];   // (1,256)
    // d_in[7] = b2: cancels in softmax, unused.

    float* out   = (float*)d_out;
    float* out_u  = out;                         // user_log_vecs: 4096*448
    float* out_nf = out + B_ * NN_ * NEWS_;      // nf:            4096*448

    void *pn_p, *plb_p, *p2_p;
    cudaGetSymbolAddress(&pn_p,  g_pn);
    cudaGetSymbolAddress(&plb_p, g_plb);
    cudaGetSymbolAddress(&p2_p,  g_P2);
    float* pn  = (float*)pn_p;
    float* plb = (float*)plb_p;
    float* P2  = (float*)p2_p;

    // 1) positional part of pl (+ b1)
    p2_kernel<<<HL_, 256>>>(pos_emb, W1, b1, P2);

    // 2) pn = news @ Wn[:, :384]^T          (pos part of nf is zero)
    gemm_wt_kernel<<<dim3(ATT_ / 64, (B_ * NN_) / 64), 256>>>(news_vec, W1, 0, nullptr, pn);

    // 3) plb = log @ Wl[:, :384]^T + P2
    gemm_wt_kernel<<<dim3(ATT_ / 64, (B_ * HL_) / 64), 256>>>(log_vec, W1, NEWS_, P2, plb);

    // 4) nf output
    {
        int total = B_ * NN_ * NEWS_;
        nf_kernel<<<(total + 255) / 256, 256>>>(news_vec, out_nf);
    }

    // 5) fused tanh-attention + softmax + weighted sum
    {
        size_t smem = (size_t)(HL_ * ATT_ + NPB * 64 * 2) * sizeof(float); // 53248
        cudaFuncSetAttribute(attn_kernel, cudaFuncAttributeMaxDynamicSharedMemorySize,
                             (int)smem);
        attn_kernel<<<dim3(NN_ / NPB, B_), 256, smem>>>(pn, plb, log_vec, pos_emb,
                                                        log_mask, W2, out_u);
    }
}

// round 5
// speedup vs baseline: 1.8202x; 1.8202x over previous
#include <cuda_runtime.h>
#include <cuda_bf16.h>
#include <cstdint>

// Problem constants
#define B_   64
#define NN_  64
#define HL_  50
#define IN_  384
#define POS_ 64
#define ATT_ 256
#define NEWS_ 448          // IN_ + POS_
#define W1STRIDE 896       // 2*NEWS_

// Scratch (no allocations allowed -> device globals)
__device__ float g_pn [B_ * NN_ * ATT_];   // 4096 x 256
__device__ float g_plb[B_ * HL_ * ATT_];   // 3200 x 256  (pl + pos-part + b1)

// ---------------------------------------------------------------------------
// Swizzled smem layout: tile is rows x 16 bf16 (32B = 2 x 16B chunks / row).
// chunk (r,c) stored at ((r*2 + (c ^ ((r>>2)&1))) * 16) bytes -> ldmatrix
// phases hit 8 distinct 16B bank groups.
// ---------------------------------------------------------------------------
#define SWOFF(r, c) ((unsigned)(((r)*2 + ((c) ^ (((r) >> 2) & 1))) << 4))

__device__ __forceinline__ uint32_t pack_bf2(__nv_bfloat16 a, __nv_bfloat16 b) {
    return (uint32_t)__bfloat16_as_ushort(a) |
           ((uint32_t)__bfloat16_as_ushort(b) << 16);
}

__device__ __forceinline__ void ldm4(uint32_t* r, uint32_t addr) {
    asm volatile("ldmatrix.sync.aligned.m8n8.x4.shared.b16 {%0,%1,%2,%3}, [%4];"
                 : "=r"(r[0]), "=r"(r[1]), "=r"(r[2]), "=r"(r[3]) : "r"(addr));
}

__device__ __forceinline__ void mma16816(float* c, const uint32_t* a,
                                         uint32_t b0, uint32_t b1) {
    asm volatile(
        "mma.sync.aligned.m16n8k16.row.col.f32.bf16.bf16.f32 "
        "{%0,%1,%2,%3}, {%4,%5,%6,%7}, {%8,%9}, {%0,%1,%2,%3};"
        : "+f"(c[0]), "+f"(c[1]), "+f"(c[2]), "+f"(c[3])
        : "r"(a[0]), "r"(a[1]), "r"(a[2]), "r"(a[3]), "r"(b0), "r"(b1));
}

// split fp32 -> (hi, lo) bf16 pair
__device__ __forceinline__ void split_bf16(float x, __nv_bfloat16& h, __nv_bfloat16& l) {
    h = __float2bfloat16_rn(x);
    l = __float2bfloat16_rn(x - __bfloat162float(h));
}

// ---------------------------------------------------------------------------
// Fused GEMM kernel (tensor cores, split-bf16 3-term fp32 emulation).
//   blockIdx.y <  64 : pn  block: C=g_pn,  A=news_vec, K=384, wOff=0
//   blockIdx.y >= 64 : plb block: C=g_plb, A=[log|pos], K=448, wOff=448, +b1
// Tile 64(M) x 64(N) x 16(K), 128 threads, warp grid 2x2 (32x32 per warp).
// ---------------------------------------------------------------------------
__global__ void gemm_both_kernel(const float* __restrict__ news,
                                 const float* __restrict__ logv,
                                 const float* __restrict__ W1,
                                 const float* __restrict__ pos_emb,
                                 const float* __restrict__ b1,
                                 float* __restrict__ pnO,
                                 float* __restrict__ plbO) {
    __shared__ __align__(16) unsigned char smem[8192];
    // offsets: AH 0..2047, AL 2048.., BH 4096.., BL 6144..
    const unsigned AH = 0, AL = 2048, BH = 4096, BL = 6144;

    const bool isPlb = (blockIdx.y >= 64);
    const int  m0 = (isPlb ? (blockIdx.y - 64) : blockIdx.y) * 64;
    const int  n0 = blockIdx.x * 64;
    const float* Aptr = isPlb ? logv : news;
    const int  wOff = isPlb ? NEWS_ : 0;
    const int  NIT  = isPlb ? (NEWS_ / 16) : (IN_ / 16);   // 28 : 24
    float* Cptr = isPlb ? plbO : pnO;

    const int tid  = threadIdx.x;
    const int lane = tid & 31;
    const int wid  = tid >> 5;
    const int wm   = wid >> 1, wn = wid & 1;

    const uint32_t sbase = (uint32_t)__cvta_generic_to_shared(smem);
    const int lrow = lane & 15, lc = lane >> 4;

    // precomputed ldmatrix addresses (constant across k-iterations)
    uint32_t aAdH[2], aAdL[2], bAdH[2], bAdL[2];
#pragma unroll
    for (int mt = 0; mt < 2; mt++) {
        int r = wm * 32 + mt * 16 + lrow;
        aAdH[mt] = sbase + AH + SWOFF(r, lc);
        aAdL[mt] = sbase + AL + SWOFF(r, lc);
    }
#pragma unroll
    for (int lm = 0; lm < 2; lm++) {
        int r = wn * 32 + lm * 16 + lrow;
        bAdH[lm] = sbase + BH + SWOFF(r, lc);
        bAdL[lm] = sbase + BL + SWOFF(r, lc);
    }

    float acc[2][4][4];
#pragma unroll
    for (int i = 0; i < 2; i++)
#pragma unroll
        for (int j = 0; j < 4; j++)
#pragma unroll
            for (int q = 0; q < 4; q++) acc[i][j][q] = 0.f;

    float4 ra[2], rb[2];

    // ---- prologue load (k0 = 0) ----
#pragma unroll
    for (int u = 0; u < 2; u++) {
        int idx = tid + u * 128;
        int row = idx >> 2, kq = idx & 3;
        int k = kq * 4;
        ra[u] = *(const float4*)(Aptr + (size_t)(m0 + row) * IN_ + k);
        rb[u] = *(const float4*)(W1 + (size_t)(n0 + row) * W1STRIDE + wOff + k);
    }

    for (int it = 0; it < NIT; ++it) {
        __syncthreads();   // previous compute done -> safe to overwrite smem

        // ---- convert + store tile to smem ----
#pragma unroll
        for (int u = 0; u < 2; u++) {
            int idx = tid + u * 128;
            int row = idx >> 2, kq = idx & 3;
            unsigned off = SWOFF(row, kq >> 1) + (kq & 1) * 8;

            __nv_bfloat16 h0, h1, h2, h3, l0, l1, l2, l3;
            float4 v = ra[u];
            split_bf16(v.x, h0, l0); split_bf16(v.y, h1, l1);
            split_bf16(v.z, h2, l2); split_bf16(v.w, h3, l3);
            *(uint2*)(smem + AH + off) = make_uint2(pack_bf2(h0, h1), pack_bf2(h2, h3));
            *(uint2*)(smem + AL + off) = make_uint2(pack_bf2(l0, l1), pack_bf2(l2, l3));

            v = rb[u];
            split_bf16(v.x, h0, l0); split_bf16(v.y, h1, l1);
            split_bf16(v.z, h2, l2); split_bf16(v.w, h3, l3);
            *(uint2*)(smem + BH + off) = make_uint2(pack_bf2(h0, h1), pack_bf2(h2, h3));
            *(uint2*)(smem + BL + off) = make_uint2(pack_bf2(l0, l1), pack_bf2(l2, l3));
        }
        __syncthreads();

        // ---- prefetch next k tile (hidden under mma) ----
        if (it + 1 < NIT) {
            int k0 = (it + 1) * 16;
#pragma unroll
            for (int u = 0; u < 2; u++) {
                int idx = tid + u * 128;
                int row = idx >> 2, kq = idx & 3;
                int k = k0 + kq * 4;
                if (!isPlb || k < IN_) {
                    ra[u] = *(const float4*)(Aptr + (size_t)(m0 + row) * IN_ + k);
                } else {
                    int h = (m0 + row) % HL_;
                    ra[u] = *(const float4*)(pos_emb + (size_t)(1 + h) * POS_ + (k - IN_));
                }
                rb[u] = *(const float4*)(W1 + (size_t)(n0 + row) * W1STRIDE + wOff + k);
            }
        }

        // ---- compute: 8 ldmatrix + 24 mma ----
        uint32_t ah[2][4], al[2][4], bh[2][4], bl[2][4];
        ldm4(ah[0], aAdH[0]); ldm4(ah[1], aAdH[1]);
        ldm4(al[0], aAdL[0]); ldm4(al[1], aAdL[1]);
        ldm4(bh[0], bAdH[0]); ldm4(bh[1], bAdH[1]);
        ldm4(bl[0], bAdL[0]); ldm4(bl[1], bAdL[1]);

#pragma unroll
        for (int mt = 0; mt < 2; mt++) {
#pragma unroll
            for (int nt = 0; nt < 4; nt++) {
                int lm = nt >> 1, s = nt & 1;
                uint32_t b0h = bh[lm][s], b1h = bh[lm][2 + s];
                uint32_t b0l = bl[lm][s], b1l = bl[lm][2 + s];
                mma16816(acc[mt][nt], ah[mt], b0h, b1h);   // hi*hi
                mma16816(acc[mt][nt], ah[mt], b0l, b1l);   // hi*lo
                mma16816(acc[mt][nt], al[mt], b0h, b1h);   // lo*hi
            }
        }
    }

    // ---- epilogue ----
    const int g = lane >> 2, tq = lane & 3;
#pragma unroll
    for (int mt = 0; mt < 2; mt++) {
        int r = m0 + wm * 32 + mt * 16 + g;
#pragma unroll
        for (int nt = 0; nt < 4; nt++) {
            int cc = n0 + wn * 32 + nt * 8 + tq * 2;
            float2 v0 = make_float2(acc[mt][nt][0], acc[mt][nt][1]);
            float2 v1 = make_float2(acc[mt][nt][2], acc[mt][nt][3]);
            if (isPlb) {
                float2 bb = *(const float2*)(b1 + cc);
                v0.x += bb.x; v0.y += bb.y;
                v1.x += bb.x; v1.y += bb.y;
            }
            *(float2*)(Cptr + (size_t)r * ATT_ + cc)       = v0;
            *(float2*)(Cptr + (size_t)(r + 8) * ATT_ + cc) = v1;
        }
    }
}

// ---------------------------------------------------------------------------
// nf output: [news_vec | zeros]  -> out_nf (4096 x 448), pure float4 copy
// ---------------------------------------------------------------------------
__global__ void nf_kernel(const float4* __restrict__ news4,
                          float4* __restrict__ out4) {
    int r = blockIdx.x, t = threadIdx.x;       // 4096 rows, 128 threads
    if (t < 96)       out4[(size_t)r * 112 + t] = news4[(size_t)r * 96 + t];
    else if (t < 112) out4[(size_t)r * 112 + t] = make_float4(0.f, 0.f, 0.f, 0.f);
}

// ---------------------------------------------------------------------------
// Fused attention: per block = (b, 4 consecutive n).
// ---------------------------------------------------------------------------
#define NPB 4
__device__ __forceinline__ float tanh_approx(float x) {
    float y;
    asm("tanh.approx.f32 %0, %1;" : "=f"(y) : "f"(x));
    return y;
}

__global__ void attn_kernel(const float* __restrict__ pn,
                            const float* __restrict__ plb,
                            const float* __restrict__ log_vec,
                            const float* __restrict__ pos_emb,
                            const int*   __restrict__ log_mask,
                            const float* __restrict__ W2,
                            float* __restrict__ out_u) {
    extern __shared__ float sm[];
    float* plb_s   = sm;                   // 50*256 = 12800
    float* logits_s = sm + HL_ * ATT_;     // NPB*64
    float* attn_s   = logits_s + NPB * 64; // NPB*64
    __shared__ int mask_s[HL_];

    const int b  = blockIdx.y;
    const int n0 = blockIdx.x * NPB;
    const int tid = threadIdx.x;
    const int lane = tid & 31, w = tid >> 5;

    // stage plb[b] (50x256) into smem, vectorized
    {
        const float4* src = (const float4*)(plb + b * HL_ * ATT_);
        float4* dst = (float4*)plb_s;
        for (int i = tid; i < HL_ * ATT_ / 4; i += 256) dst[i] = src[i];
    }
    if (tid < HL_) mask_s[tid] = log_mask[b * HL_ + tid];

    // per-thread registers: pn rows + W2, a = lane + 32*j8
    float pnr[NPB][8], w2r[8];
    #pragma unroll
    for (int j8 = 0; j8 < 8; j8++) {
        int a = lane + 32 * j8;
        w2r[j8] = W2[a];
        #pragma unroll
        for (int j = 0; j < NPB; j++)
            pnr[j][j8] = pn[(b * NN_ + n0 + j) * ATT_ + a];
    }
    __syncthreads();

    // main loop: warp w handles h = w, w+8, ...
    for (int h = w; h < HL_; h += 8) {
        float acc[NPB] = {0.f, 0.f, 0.f, 0.f};
        #pragma unroll
        for (int j8 = 0; j8 < 8; j8++) {
            float pl = plb_s[h * ATT_ + lane + 32 * j8];
            #pragma unroll
            for (int j = 0; j < NPB; j++) {
                float t = tanh_approx(pl + pnr[j][j8]);
                acc[j] = fmaf(t, w2r[j8], acc[j]);
            }
        }
        #pragma unroll
        for (int j = 0; j < NPB; j++) {
            float v = acc[j];
            v += __shfl_xor_sync(0xffffffffu, v, 16);
            v += __shfl_xor_sync(0xffffffffu, v, 8);
            v += __shfl_xor_sync(0xffffffffu, v, 4);
            v += __shfl_xor_sync(0xffffffffu, v, 2);
            v += __shfl_xor_sync(0xffffffffu, v, 1);
            if (lane == 0) logits_s[j * 64 + h] = v;
        }
    }
    __syncthreads();

    // masked softmax: warp j (< NPB) handles row j
    if (w < NPB) {
        const int j = w;
        int h0 = lane, h1 = lane + 32;
        float v0 = -3e38f, v1 = -3e38f;
        if (h0 < HL_) v0 = (mask_s[h0] == 0) ? -1e9f : logits_s[j * 64 + h0];
        if (h1 < HL_) v1 = (mask_s[h1] == 0) ? -1e9f : logits_s[j * 64 + h1];
        float m = fmaxf(v0, v1);
        #pragma unroll
        for (int s = 16; s; s >>= 1) m = fmaxf(m, __shfl_xor_sync(0xffffffffu, m, s));
        float e0 = (h0 < HL_) ? __expf(v0 - m) : 0.f;
        float e1 = (h1 < HL_) ? __expf(v1 - m) : 0.f;
        float ssum = e0 + e1;
        #pragma unroll
        for (int s = 16; s; s >>= 1) ssum += __shfl_xor_sync(0xffffffffu, ssum, s);
        float inv = 1.f / ssum;
        if (h0 < HL_) attn_s[j * 64 + h0] = e0 * inv;
        if (h1 < HL_) attn_s[j * 64 + h1] = e1 * inv;
    }
    __syncthreads();

    // epilogue: out[b, n0+j, d] = sum_h attn[j,h] * lf[b,h,d]
    for (int d = tid; d < NEWS_; d += 256) {
        float acc[NPB] = {0.f, 0.f, 0.f, 0.f};
        if (d < IN_) {
            for (int h = 0; h < HL_; h++) {
                float lv = log_vec[(b * HL_ + h) * IN_ + d];
                #pragma unroll
                for (int j = 0; j < NPB; j++)
                    acc[j] = fmaf(attn_s[j * 64 + h], lv, acc[j]);
            }
        } else {
            int dp = d - IN_;
            for (int h = 0; h < HL_; h++) {
                float lv = pos_emb[(1 + h) * POS_ + dp];
                #pragma unroll
                for (int j = 0; j < NPB; j++)
                    acc[j] = fmaf(attn_s[j * 64 + h], lv, acc[j]);
            }
        }
        #pragma unroll
        for (int j = 0; j < NPB; j++)
            out_u[(b * NN_ + n0 + j) * NEWS_ + d] = acc[j];
    }
}

// ---------------------------------------------------------------------------
extern "C" void kernel_launch(void* const* d_in, const int* in_sizes, int n_in,
                              void* d_out, int out_size) {
    const float* log_vec  = (const float*)d_in[0];   // (64,50,384)
    const int*   log_mask = (const int*)  d_in[1];   // (64,50)
    const float* news_vec = (const float*)d_in[2];   // (64,64,384)
    const float* pos_emb  = (const float*)d_in[3];   // (100,64)
    const float* W1       = (const float*)d_in[4];   // (256,896)
    const float* b1       = (const float*)d_in[5];   // (256)
    const float* W2       = (const float*)d_in[6];   // (1,256)
    // d_in[7] = b2: cancels in softmax, unused.

    float* out    = (float*)d_out;
    float* out_u  = out;                         // user_log_vecs: 4096*448
    float* out_nf = out + B_ * NN_ * NEWS_;      // nf:            4096*448

    void *pn_p, *plb_p;
    cudaGetSymbolAddress(&pn_p,  g_pn);
    cudaGetSymbolAddress(&plb_p, g_plb);
    float* pn  = (float*)pn_p;
    float* plb = (float*)plb_p;

    // 1) both projection GEMMs (tensor cores, split-bf16), one launch:
    //    grid.y 0..63 -> pn (4096x256, K=384); 64..113 -> plb (3200x256, K=448)
    gemm_both_kernel<<<dim3(ATT_ / 64, 64 + 50), 128>>>(
        news_vec, log_vec, W1, pos_emb, b1, pn, plb);

    // 2) nf output (independent)
    nf_kernel<<<B_ * NN_, 128>>>((const float4*)news_vec, (float4*)out_nf);

    // 3) fused tanh-attention + softmax + weighted sum
    {
        size_t smem = (size_t)(HL_ * ATT_ + NPB * 64 * 2) * sizeof(float); // 53248
        cudaFuncSetAttribute(attn_kernel, cudaFuncAttributeMaxDynamicSharedMemorySize,
                             (int)smem);
        attn_kernel<<<dim3(NN_ / NPB, B_), 256, smem>>>(pn, plb, log_vec, pos_emb,
                                                        log_mask, W2, out_u);
    }
}

// round 6
// speedup vs baseline: 1.8824x; 1.0342x over previous
#include <cuda_runtime.h>
#include <cuda_bf16.h>
#include <cstdint>

// Problem constants
#define B_   64
#define NN_  64
#define HL_  50
#define IN_  384
#define POS_ 64
#define ATT_ 256
#define NEWS_ 448          // IN_ + POS_
#define W1STRIDE 896       // 2*NEWS_

// Scratch (no allocations allowed -> device globals)
__device__ float g_pn [B_ * NN_ * ATT_];   // 4096 x 256
__device__ float g_plb[B_ * HL_ * ATT_];   // 3200 x 256

// bf16 hi/lo prepped operands
__device__ __nv_bfloat16 g_Ah_pn [B_ * NN_ * IN_];    // 4096 x 384
__device__ __nv_bfloat16 g_Al_pn [B_ * NN_ * IN_];
__device__ __nv_bfloat16 g_Ah_plb[B_ * HL_ * NEWS_];  // 3200 x 448 ([log|pos])
__device__ __nv_bfloat16 g_Al_plb[B_ * HL_ * NEWS_];
__device__ __nv_bfloat16 g_Bh_pn [ATT_ * IN_];        // 256 x 384 (W1[:, :384])
__device__ __nv_bfloat16 g_Bl_pn [ATT_ * IN_];
__device__ __nv_bfloat16 g_Bh_plb[ATT_ * NEWS_];      // 256 x 448 (W1[:, 448:])
__device__ __nv_bfloat16 g_Bl_plb[ATT_ * NEWS_];

// ---------------------------------------------------------------------------
// helpers
// ---------------------------------------------------------------------------
#define SWOFF(r, c) ((unsigned)(((r)*2 + ((c) ^ (((r) >> 2) & 1))) << 4))

__device__ __forceinline__ uint32_t pack_bf2(__nv_bfloat16 a, __nv_bfloat16 b) {
    return (uint32_t)__bfloat16_as_ushort(a) |
           ((uint32_t)__bfloat16_as_ushort(b) << 16);
}
__device__ __forceinline__ void split_bf16(float x, __nv_bfloat16& h, __nv_bfloat16& l) {
    h = __float2bfloat16_rn(x);
    l = __float2bfloat16_rn(x - __bfloat162float(h));
}
// split a float4 into hi/lo uint2 packets
__device__ __forceinline__ void split4(float4 v, uint2& hi, uint2& lo) {
    __nv_bfloat16 h0,h1,h2,h3,l0,l1,l2,l3;
    split_bf16(v.x,h0,l0); split_bf16(v.y,h1,l1);
    split_bf16(v.z,h2,l2); split_bf16(v.w,h3,l3);
    hi = make_uint2(pack_bf2(h0,h1), pack_bf2(h2,h3));
    lo = make_uint2(pack_bf2(l0,l1), pack_bf2(l2,l3));
}
__device__ __forceinline__ void ldm4(uint32_t* r, uint32_t addr) {
    asm volatile("ldmatrix.sync.aligned.m8n8.x4.shared.b16 {%0,%1,%2,%3}, [%4];"
                 : "=r"(r[0]), "=r"(r[1]), "=r"(r[2]), "=r"(r[3]) : "r"(addr));
}
__device__ __forceinline__ void mma16816(float* c, const uint32_t* a,
                                         uint32_t b0, uint32_t b1) {
    asm volatile(
        "mma.sync.aligned.m16n8k16.row.col.f32.bf16.bf16.f32 "
        "{%0,%1,%2,%3}, {%4,%5,%6,%7}, {%8,%9}, {%0,%1,%2,%3};"
        : "+f"(c[0]), "+f"(c[1]), "+f"(c[2]), "+f"(c[3])
        : "r"(a[0]), "r"(a[1]), "r"(a[2]), "r"(a[3]), "r"(b0), "r"(b1));
}
__device__ __forceinline__ void cp16(uint32_t dst, const void* src) {
    asm volatile("cp.async.cg.shared.global [%0], [%1], 16;" :: "r"(dst), "l"(src));
}
__device__ __forceinline__ void cp_commit() { asm volatile("cp.async.commit_group;"); }
template<int N> __device__ __forceinline__ void cp_wait() {
    asm volatile("cp.async.wait_group %0;" :: "n"(N));
}

// ---------------------------------------------------------------------------
// Prep: convert all operands to bf16 hi/lo once, and write the nf output.
//   blocks    0..4095 : news row r -> A_pn row + nf output row
//   blocks 4096..7295 : log row lr -> A_plb row ([log(384) | pos(64)])
//   blocks 7296..7551 : W1 row w   -> B_pn row (cols 0..383), B_plb row (448..895)
// 128 threads, one float4 per thread.
// ---------------------------------------------------------------------------
__global__ void prep_kernel(const float* __restrict__ log_vec,
                            const float* __restrict__ news_vec,
                            const float* __restrict__ pos_emb,
                            const float* __restrict__ W1,
                            float* __restrict__ out_nf) {
    const int r = blockIdx.x, t = threadIdx.x;
    if (r < 4096) {
        // news: convert + nf copy
        float4* nf4 = (float4*)(out_nf + (size_t)r * NEWS_);
        if (t < 96) {
            float4 v = *(const float4*)(news_vec + (size_t)r * IN_ + t * 4);
            uint2 hi, lo; split4(v, hi, lo);
            *(uint2*)(g_Ah_pn + (size_t)r * IN_ + t * 4) = hi;
            *(uint2*)(g_Al_pn + (size_t)r * IN_ + t * 4) = lo;
            nf4[t] = v;
        } else if (t < 112) {
            nf4[t] = make_float4(0.f, 0.f, 0.f, 0.f);
        }
    } else if (r < 7296) {
        const int lr = r - 4096;
        const int h = lr % HL_;
        if (t < 112) {
            float4 v;
            if (t < 96) v = *(const float4*)(log_vec + (size_t)lr * IN_ + t * 4);
            else        v = *(const float4*)(pos_emb + (size_t)(1 + h) * POS_ + (t - 96) * 4);
            uint2 hi, lo; split4(v, hi, lo);
            *(uint2*)(g_Ah_plb + (size_t)lr * NEWS_ + t * 4) = hi;
            *(uint2*)(g_Al_plb + (size_t)lr * NEWS_ + t * 4) = lo;
        }
    } else {
        const int w = r - 7296;   // 0..255
        if (t < 96) {
            float4 v = *(const float4*)(W1 + (size_t)w * W1STRIDE + t * 4);
            uint2 hi, lo; split4(v, hi, lo);
            *(uint2*)(g_Bh_pn + (size_t)w * IN_ + t * 4) = hi;
            *(uint2*)(g_Bl_pn + (size_t)w * IN_ + t * 4) = lo;
        }
        if (t < 112) {
            float4 v = *(const float4*)(W1 + (size_t)w * W1STRIDE + NEWS_ + t * 4);
            uint2 hi, lo; split4(v, hi, lo);
            *(uint2*)(g_Bh_plb + (size_t)w * NEWS_ + t * 4) = hi;
            *(uint2*)(g_Bl_plb + (size_t)w * NEWS_ + t * 4) = lo;
        }
    }
}

// ---------------------------------------------------------------------------
// GEMM v2: pure tensor-core mainloop (cp.async 4-stage -> ldmatrix -> mma).
//   blockIdx.y <  64 : pn  (A=g_A*_pn,  B=g_B*_pn,  K=384)
//   blockIdx.y >= 64 : plb (A=g_A*_plb, B=g_B*_plb, K=448, +b1 epilogue)
// Tile 64x64x16, 128 threads, warp grid 2x2 (32x32 per warp), 3-term split.
// ---------------------------------------------------------------------------
#define NSTG 4
__global__ void gemm_tc_kernel(const float* __restrict__ b1) {
    __shared__ __align__(16) unsigned char smem[NSTG * 8192];
    const unsigned MOFF[4] = {0u, 2048u, 4096u, 6144u};   // AH, AL, BH, BL

    const bool isPlb = (blockIdx.y >= 64);
    const int  m0 = (isPlb ? (blockIdx.y - 64) : blockIdx.y) * 64;
    const int  n0 = blockIdx.x * 64;
    const int  K   = isPlb ? NEWS_ : IN_;
    const int  NIT = K / 16;
    const __nv_bfloat16* Ah = isPlb ? g_Ah_plb : g_Ah_pn;
    const __nv_bfloat16* Al = isPlb ? g_Al_plb : g_Al_pn;
    const __nv_bfloat16* Bh = isPlb ? g_Bh_plb : g_Bh_pn;
    const __nv_bfloat16* Bl = isPlb ? g_Bl_plb : g_Bl_pn;
    float* Cptr = isPlb ? g_plb : g_pn;

    const int tid  = threadIdx.x;
    const int lane = tid & 31;
    const int wid  = tid >> 5;
    const int wm   = wid >> 1, wn = wid & 1;
    const uint32_t sbase = (uint32_t)__cvta_generic_to_shared(smem);

    // cp.async source row pointers / smem dsts for this thread (4 chunks/stage)
    const __nv_bfloat16* srcRow[4];
    uint32_t dstOff[4];
    int kadd[4];
#pragma unroll
    for (int u = 0; u < 4; u++) {
        int idx = tid + u * 128;            // 0..511
        int mat = idx >> 7;                 // 0 AH, 1 AL, 2 BH, 3 BL
        int j   = idx & 127;
        int rr  = j >> 1, cc = j & 1;
        const __nv_bfloat16* base = (mat == 0) ? Ah : (mat == 1) ? Al
                                   : (mat == 2) ? Bh : Bl;
        int row = (mat < 2) ? (m0 + rr) : (n0 + rr);
        srcRow[u] = base + (size_t)row * K + cc * 8;
        dstOff[u] = MOFF[mat] + SWOFF(rr, cc);
        kadd[u]   = 0;
        (void)kadd;
    }

    // ldmatrix addresses (per-stage offset added at use)
    const int lrow = lane & 15, lc = lane >> 4;
    uint32_t aAdH[2], aAdL[2], bAdH[2], bAdL[2];
#pragma unroll
    for (int mt = 0; mt < 2; mt++) {
        int r = wm * 32 + mt * 16 + lrow;
        aAdH[mt] = sbase + MOFF[0] + SWOFF(r, lc);
        aAdL[mt] = sbase + MOFF[1] + SWOFF(r, lc);
    }
#pragma unroll
    for (int lm = 0; lm < 2; lm++) {
        int r = wn * 32 + lm * 16 + lrow;
        bAdH[lm] = sbase + MOFF[2] + SWOFF(r, lc);
        bAdL[lm] = sbase + MOFF[3] + SWOFF(r, lc);
    }

    float acc[2][4][4];
#pragma unroll
    for (int i = 0; i < 2; i++)
#pragma unroll
        for (int j = 0; j < 4; j++)
#pragma unroll
            for (int q = 0; q < 4; q++) acc[i][j][q] = 0.f;

    // prologue: stages 0..NSTG-2
#pragma unroll
    for (int s = 0; s < NSTG - 1; s++) {
#pragma unroll
        for (int u = 0; u < 4; u++)
            cp16(sbase + s * 8192 + dstOff[u], srcRow[u] + s * 16);
        cp_commit();
    }

    for (int it = 0; it < NIT; ++it) {
        cp_wait<NSTG - 2>();
        __syncthreads();

        // issue stage it+NSTG-1 (overwrites buffer computed at it-1)
        if (it + NSTG - 1 < NIT) {
            int st = (it + NSTG - 1) & (NSTG - 1);
#pragma unroll
            for (int u = 0; u < 4; u++)
                cp16(sbase + st * 8192 + dstOff[u], srcRow[u] + (it + NSTG - 1) * 16);
        }
        cp_commit();

        // compute stage it
        const uint32_t so = (uint32_t)((it & (NSTG - 1)) * 8192);
        uint32_t ah[2][4], al[2][4], bh[2][4], bl[2][4];
        ldm4(ah[0], aAdH[0] + so); ldm4(ah[1], aAdH[1] + so);
        ldm4(al[0], aAdL[0] + so); ldm4(al[1], aAdL[1] + so);
        ldm4(bh[0], bAdH[0] + so); ldm4(bh[1], bAdH[1] + so);
        ldm4(bl[0], bAdL[0] + so); ldm4(bl[1], bAdL[1] + so);

#pragma unroll
        for (int mt = 0; mt < 2; mt++) {
#pragma unroll
            for (int nt = 0; nt < 4; nt++) {
                int lm = nt >> 1, s = nt & 1;
                uint32_t b0h = bh[lm][s], b1h = bh[lm][2 + s];
                uint32_t b0l = bl[lm][s], b1l = bl[lm][2 + s];
                mma16816(acc[mt][nt], ah[mt], b0h, b1h);   // hi*hi
                mma16816(acc[mt][nt], ah[mt], b0l, b1l);   // hi*lo
                mma16816(acc[mt][nt], al[mt], b0h, b1h);   // lo*hi
            }
        }
        __syncthreads();
    }

    // epilogue
    const int g = lane >> 2, tq = lane & 3;
#pragma unroll
    for (int mt = 0; mt < 2; mt++) {
        int r = m0 + wm * 32 + mt * 16 + g;
#pragma unroll
        for (int nt = 0; nt < 4; nt++) {
            int cc = n0 + wn * 32 + nt * 8 + tq * 2;
            float2 v0 = make_float2(acc[mt][nt][0], acc[mt][nt][1]);
            float2 v1 = make_float2(acc[mt][nt][2], acc[mt][nt][3]);
            if (isPlb) {
                float2 bb = *(const float2*)(b1 + cc);
                v0.x += bb.x; v0.y += bb.y;
                v1.x += bb.x; v1.y += bb.y;
            }
            *(float2*)(Cptr + (size_t)r * ATT_ + cc)       = v0;
            *(float2*)(Cptr + (size_t)(r + 8) * ATT_ + cc) = v1;
        }
    }
}

// ---------------------------------------------------------------------------
// Fused attention: per block = (b, 8 consecutive n). 256 threads / 8 warps.
// ---------------------------------------------------------------------------
#define NPB 8
__device__ __forceinline__ float tanh_approx(float x) {
    float y;
    asm("tanh.approx.f32 %0, %1;" : "=f"(y) : "f"(x));
    return y;
}

__global__ void attn_kernel(const float* __restrict__ log_vec,
                            const float* __restrict__ pos_emb,
                            const int*   __restrict__ log_mask,
                            const float* __restrict__ W2,
                            float* __restrict__ out_u) {
    extern __shared__ float sm[];
    float* plb_s    = sm;                    // 50*256 = 12800
    float* logits_s = sm + HL_ * ATT_;       // NPB*64
    float* attn_s   = logits_s + NPB * 64;   // NPB*64
    __shared__ int mask_s[HL_];

    const int b  = blockIdx.y;
    const int n0 = blockIdx.x * NPB;
    const int tid = threadIdx.x;
    const int lane = tid & 31, w = tid >> 5;

    // stage plb[b] (50x256) into smem
    {
        const float4* src = (const float4*)(g_plb + b * HL_ * ATT_);
        float4* dst = (float4*)plb_s;
        for (int i = tid; i < HL_ * ATT_ / 4; i += 256) dst[i] = src[i];
    }
    if (tid < HL_) mask_s[tid] = log_mask[b * HL_ + tid];

    // per-thread registers: pn rows + W2, a = lane + 32*j8
    float pnr[NPB][8], w2r[8];
    #pragma unroll
    for (int j8 = 0; j8 < 8; j8++) {
        int a = lane + 32 * j8;
        w2r[j8] = W2[a];
        #pragma unroll
        for (int j = 0; j < NPB; j++)
            pnr[j][j8] = g_pn[(b * NN_ + n0 + j) * ATT_ + a];
    }
    __syncthreads();

    // main loop: warp w handles h = w, w+8, ...
    for (int h = w; h < HL_; h += 8) {
        float acc[NPB];
        #pragma unroll
        for (int j = 0; j < NPB; j++) acc[j] = 0.f;
        #pragma unroll
        for (int j8 = 0; j8 < 8; j8++) {
            float pl = plb_s[h * ATT_ + lane + 32 * j8];
            #pragma unroll
            for (int j = 0; j < NPB; j++) {
                float t = tanh_approx(pl + pnr[j][j8]);
                acc[j] = fmaf(t, w2r[j8], acc[j]);
            }
        }
        #pragma unroll
        for (int j = 0; j < NPB; j++) {
            float v = acc[j];
            v += __shfl_xor_sync(0xffffffffu, v, 16);
            v += __shfl_xor_sync(0xffffffffu, v, 8);
            v += __shfl_xor_sync(0xffffffffu, v, 4);
            v += __shfl_xor_sync(0xffffffffu, v, 2);
            v += __shfl_xor_sync(0xffffffffu, v, 1);
            if (lane == 0) logits_s[j * 64 + h] = v;
        }
    }
    __syncthreads();

    // masked softmax: warp j handles row j (8 warps = NPB rows)
    {
        const int j = w;
        int h0 = lane, h1 = lane + 32;
        float v0 = -3e38f, v1 = -3e38f;
        if (h0 < HL_) v0 = (mask_s[h0] == 0) ? -1e9f : logits_s[j * 64 + h0];
        if (h1 < HL_) v1 = (mask_s[h1] == 0) ? -1e9f : logits_s[j * 64 + h1];
        float m = fmaxf(v0, v1);
        #pragma unroll
        for (int s = 16; s; s >>= 1) m = fmaxf(m, __shfl_xor_sync(0xffffffffu, m, s));
        float e0 = (h0 < HL_) ? __expf(v0 - m) : 0.f;
        float e1 = (h1 < HL_) ? __expf(v1 - m) : 0.f;
        float ssum = e0 + e1;
        #pragma unroll
        for (int s = 16; s; s >>= 1) ssum += __shfl_xor_sync(0xffffffffu, ssum, s);
        float inv = 1.f / ssum;
        if (h0 < HL_) attn_s[j * 64 + h0] = e0 * inv;
        if (h1 < HL_) attn_s[j * 64 + h1] = e1 * inv;
    }
    __syncthreads();

    // epilogue: out[b, n0+j, d] = sum_h attn[j,h] * lf[b,h,d]
    for (int d = tid; d < NEWS_; d += 256) {
        float acc[NPB];
        #pragma unroll
        for (int j = 0; j < NPB; j++) acc[j] = 0.f;
        if (d < IN_) {
            for (int h = 0; h < HL_; h++) {
                float lv = log_vec[(b * HL_ + h) * IN_ + d];
                #pragma unroll
                for (int j = 0; j < NPB; j++)
                    acc[j] = fmaf(attn_s[j * 64 + h], lv, acc[j]);
            }
        } else {
            int dp = d - IN_;
            for (int h = 0; h < HL_; h++) {
                float lv = pos_emb[(1 + h) * POS_ + dp];
                #pragma unroll
                for (int j = 0; j < NPB; j++)
                    acc[j] = fmaf(attn_s[j * 64 + h], lv, acc[j]);
            }
        }
        #pragma unroll
        for (int j = 0; j < NPB; j++)
            out_u[(b * NN_ + n0 + j) * NEWS_ + d] = acc[j];
    }
}

// ---------------------------------------------------------------------------
extern "C" void kernel_launch(void* const* d_in, const int* in_sizes, int n_in,
                              void* d_out, int out_size) {
    const float* log_vec  = (const float*)d_in[0];   // (64,50,384)
    const int*   log_mask = (const int*)  d_in[1];   // (64,50)
    const float* news_vec = (const float*)d_in[2];   // (64,64,384)
    const float* pos_emb  = (const float*)d_in[3];   // (100,64)
    const float* W1       = (const float*)d_in[4];   // (256,896)
    const float* b1       = (const float*)d_in[5];   // (256)
    const float* W2       = (const float*)d_in[6];   // (1,256)
    // d_in[7] = b2: cancels in softmax, unused.

    float* out    = (float*)d_out;
    float* out_u  = out;                         // user_log_vecs: 4096*448
    float* out_nf = out + B_ * NN_ * NEWS_;      // nf:            4096*448

    // 1) convert operands to bf16 hi/lo + emit nf output
    prep_kernel<<<7552, 128>>>(log_vec, news_vec, pos_emb, W1, out_nf);

    // 2) both projection GEMMs on tensor cores (one launch)
    gemm_tc_kernel<<<dim3(ATT_ / 64, 64 + 50), 128>>>(b1);

    // 3) fused tanh-attention + softmax + weighted sum
    {
        size_t smem = (size_t)(HL_ * ATT_ + NPB * 64 * 2) * sizeof(float); // 55296
        cudaFuncSetAttribute(attn_kernel, cudaFuncAttributeMaxDynamicSharedMemorySize,
                             (int)smem);
        attn_kernel<<<dim3(NN_ / NPB, B_), 256, smem>>>(log_vec, pos_emb,
                                                        log_mask, W2, out_u);
    }
}

// round 7
// speedup vs baseline: 2.0276x; 1.0771x over previous
#include <cuda_runtime.h>
#include <cuda_bf16.h>
#include <cstdint>

// Problem constants
#define B_   64
#define NN_  64
#define HL_  50
#define IN_  384
#define POS_ 64
#define ATT_ 256
#define NEWS_ 448          // IN_ + POS_
#define W1STRIDE 896       // 2*NEWS_

// Scratch (no allocations allowed -> device globals)
__device__ float g_pn [B_ * NN_ * ATT_];   // 4096 x 256
__device__ float g_plb[B_ * HL_ * ATT_];   // 3200 x 256

// bf16 hi/lo prepped operands
__device__ __nv_bfloat16 g_Ah_pn [B_ * NN_ * IN_];    // 4096 x 384
__device__ __nv_bfloat16 g_Al_pn [B_ * NN_ * IN_];
__device__ __nv_bfloat16 g_Ah_plb[B_ * HL_ * NEWS_];  // 3200 x 448 ([log|pos])
__device__ __nv_bfloat16 g_Al_plb[B_ * HL_ * NEWS_];
__device__ __nv_bfloat16 g_Bh_pn [ATT_ * IN_];        // 256 x 384 (W1[:, :384])
__device__ __nv_bfloat16 g_Bl_pn [ATT_ * IN_];
__device__ __nv_bfloat16 g_Bh_plb[ATT_ * NEWS_];      // 256 x 448 (W1[:, 448:])
__device__ __nv_bfloat16 g_Bl_plb[ATT_ * NEWS_];

// ---------------------------------------------------------------------------
// helpers
// ---------------------------------------------------------------------------
// 32k-wide stage swizzle: row r (0..63) has 4 16B chunks c (0..3).
// group(r,c) = (4r + (c ^ ((r>>1)&3))) mod 8 -> distinct for 8 consecutive
// rows at fixed c => conflict-free ldmatrix phases.
#define SWOFF32(r, c) ((unsigned)(((((r) << 2) + ((c) ^ (((r) >> 1) & 3)))) << 4))

__device__ __forceinline__ uint32_t pack_bf2(__nv_bfloat16 a, __nv_bfloat16 b) {
    return (uint32_t)__bfloat16_as_ushort(a) |
           ((uint32_t)__bfloat16_as_ushort(b) << 16);
}
__device__ __forceinline__ void split_bf16(float x, __nv_bfloat16& h, __nv_bfloat16& l) {
    h = __float2bfloat16_rn(x);
    l = __float2bfloat16_rn(x - __bfloat162float(h));
}
__device__ __forceinline__ void split4(float4 v, uint2& hi, uint2& lo) {
    __nv_bfloat16 h0,h1,h2,h3,l0,l1,l2,l3;
    split_bf16(v.x,h0,l0); split_bf16(v.y,h1,l1);
    split_bf16(v.z,h2,l2); split_bf16(v.w,h3,l3);
    hi = make_uint2(pack_bf2(h0,h1), pack_bf2(h2,h3));
    lo = make_uint2(pack_bf2(l0,l1), pack_bf2(l2,l3));
}
__device__ __forceinline__ void ldm4(uint32_t* r, uint32_t addr) {
    asm volatile("ldmatrix.sync.aligned.m8n8.x4.shared.b16 {%0,%1,%2,%3}, [%4];"
                 : "=r"(r[0]), "=r"(r[1]), "=r"(r[2]), "=r"(r[3]) : "r"(addr));
}
__device__ __forceinline__ void mma16816(float* c, const uint32_t* a,
                                         uint32_t b0, uint32_t b1) {
    asm volatile(
        "mma.sync.aligned.m16n8k16.row.col.f32.bf16.bf16.f32 "
        "{%0,%1,%2,%3}, {%4,%5,%6,%7}, {%8,%9}, {%0,%1,%2,%3};"
        : "+f"(c[0]), "+f"(c[1]), "+f"(c[2]), "+f"(c[3])
        : "r"(a[0]), "r"(a[1]), "r"(a[2]), "r"(a[3]), "r"(b0), "r"(b1));
}
__device__ __forceinline__ void cp16(uint32_t dst, const void* src) {
    asm volatile("cp.async.cg.shared.global [%0], [%1], 16;" :: "r"(dst), "l"(src));
}
__device__ __forceinline__ void cp_commit() { asm volatile("cp.async.commit_group;"); }
template<int N> __device__ __forceinline__ void cp_wait() {
    asm volatile("cp.async.wait_group %0;" :: "n"(N));
}
__device__ __forceinline__ float tanh_approx(float x) {
    float y;
    asm("tanh.approx.f32 %0, %1;" : "=f"(y) : "f"(x));
    return y;
}

// ---------------------------------------------------------------------------
// Prep v2: flat one-float4-task per thread, zero idle lanes.
//   tasks [0, 458752):        news rows (4096 x 112): convert + nf out
//   tasks [458752, 817152):   log rows  (3200 x 112): [log|pos] convert
//   tasks [817152, 870400):   W1 rows   (256 x 208):  B_pn (96) + B_plb (112)
// grid = 870400 / 256 = 3400 blocks.
// ---------------------------------------------------------------------------
__global__ void prep_kernel(const float* __restrict__ log_vec,
                            const float* __restrict__ news_vec,
                            const float* __restrict__ pos_emb,
                            const float* __restrict__ W1,
                            float* __restrict__ out_nf) {
    const int gid = blockIdx.x * 256 + threadIdx.x;
    if (gid < 458752) {
        const int r = gid / 112, t = gid % 112;
        float4* nf4 = (float4*)(out_nf + (size_t)r * NEWS_);
        if (t < 96) {
            float4 v = *(const float4*)(news_vec + (size_t)r * IN_ + t * 4);
            uint2 hi, lo; split4(v, hi, lo);
            *(uint2*)(g_Ah_pn + (size_t)r * IN_ + t * 4) = hi;
            *(uint2*)(g_Al_pn + (size_t)r * IN_ + t * 4) = lo;
            nf4[t] = v;
        } else {
            nf4[t] = make_float4(0.f, 0.f, 0.f, 0.f);
        }
    } else if (gid < 817152) {
        const int g2 = gid - 458752;
        const int lr = g2 / 112, t = g2 % 112;
        float4 v;
        if (t < 96) v = *(const float4*)(log_vec + (size_t)lr * IN_ + t * 4);
        else        v = *(const float4*)(pos_emb + (size_t)(1 + lr % HL_) * POS_ + (t - 96) * 4);
        uint2 hi, lo; split4(v, hi, lo);
        *(uint2*)(g_Ah_plb + (size_t)lr * NEWS_ + t * 4) = hi;
        *(uint2*)(g_Al_plb + (size_t)lr * NEWS_ + t * 4) = lo;
    } else {
        const int g3 = gid - 817152;
        const int w = g3 / 208, t = g3 % 208;
        if (t < 96) {
            float4 v = *(const float4*)(W1 + (size_t)w * W1STRIDE + t * 4);
            uint2 hi, lo; split4(v, hi, lo);
            *(uint2*)(g_Bh_pn + (size_t)w * IN_ + t * 4) = hi;
            *(uint2*)(g_Bl_pn + (size_t)w * IN_ + t * 4) = lo;
        } else {
            const int t2 = t - 96;   // 0..111
            float4 v = *(const float4*)(W1 + (size_t)w * W1STRIDE + NEWS_ + t2 * 4);
            uint2 hi, lo; split4(v, hi, lo);
            *(uint2*)(g_Bh_plb + (size_t)w * NEWS_ + t2 * 4) = hi;
            *(uint2*)(g_Bl_plb + (size_t)w * NEWS_ + t2 * 4) = lo;
        }
    }
}

// ---------------------------------------------------------------------------
// GEMM v3: 32-k stages, 3-stage cp.async ring, ONE barrier per stage.
//   blockIdx.y <  64 : pn  (K=384, 12 stages)
//   blockIdx.y >= 64 : plb (K=448, 14 stages, +b1 epilogue)
// Tile 64x64, 128 threads, warp grid 2x2 (32x32/warp), 3-term bf16 split.
// Stage = 16KB: AH@0, AL@4096, BH@8192, BL@12288 (4KB each: 64 rows x 64B).
// ---------------------------------------------------------------------------
__global__ void gemm_tc_kernel(const float* __restrict__ b1) {
    __shared__ __align__(16) unsigned char smem[3 * 16384];   // 48KB

    const bool isPlb = (blockIdx.y >= 64);
    const int  m0 = (isPlb ? (blockIdx.y - 64) : blockIdx.y) * 64;
    const int  n0 = blockIdx.x * 64;
    const int  K   = isPlb ? NEWS_ : IN_;
    const int  NIT = K / 32;                      // 14 : 12
    const __nv_bfloat16* Abase[2] = { isPlb ? g_Ah_plb : g_Ah_pn,
                                      isPlb ? g_Al_plb : g_Al_pn };
    const __nv_bfloat16* Bbase[2] = { isPlb ? g_Bh_plb : g_Bh_pn,
                                      isPlb ? g_Bl_plb : g_Bl_pn };
    float* Cptr = isPlb ? g_plb : g_pn;

    const int tid  = threadIdx.x;
    const int lane = tid & 31;
    const int wid  = tid >> 5;
    const int wm   = wid >> 1, wn = wid & 1;
    const uint32_t sbase = (uint32_t)__cvta_generic_to_shared(smem);

    // cp.async mapping: 1024 chunks/stage, 8 per thread, coalesced.
    const __nv_bfloat16* srcB[8];
    uint32_t dstOff[8];
#pragma unroll
    for (int u = 0; u < 8; u++) {
        int flat = u * 128 + tid;            // 0..1023
        int mat  = flat >> 8;                // 0 AH, 1 AL, 2 BH, 3 BL
        int j    = flat & 255;
        int rr   = j >> 2, cc = j & 3;
        const __nv_bfloat16* base = (mat == 0) ? Abase[0] : (mat == 1) ? Abase[1]
                                  : (mat == 2) ? Bbase[0] : Bbase[1];
        int row = (mat < 2) ? (m0 + rr) : (n0 + rr);
        srcB[u]   = base + (size_t)row * K + cc * 8;
        dstOff[u] = (uint32_t)(mat * 4096) + SWOFF32(rr, cc);
    }

    // ldmatrix addresses: [hl][tile][ks]
    const int lrow = lane & 15, lc = lane >> 4;
    uint32_t aAd[2][2][2], bAd[2][2][2];
#pragma unroll
    for (int hl = 0; hl < 2; hl++) {
#pragma unroll
        for (int mt = 0; mt < 2; mt++) {
            int r = wm * 32 + mt * 16 + lrow;
#pragma unroll
            for (int ks = 0; ks < 2; ks++)
                aAd[hl][mt][ks] = sbase + hl * 4096 + SWOFF32(r, 2 * ks + lc);
        }
#pragma unroll
        for (int lm = 0; lm < 2; lm++) {
            int r = wn * 32 + lm * 16 + lrow;
#pragma unroll
            for (int ks = 0; ks < 2; ks++)
                bAd[hl][lm][ks] = sbase + (2 + hl) * 4096 + SWOFF32(r, 2 * ks + lc);
        }
    }

    float acc[2][4][4];
#pragma unroll
    for (int i = 0; i < 2; i++)
#pragma unroll
        for (int j = 0; j < 4; j++)
#pragma unroll
            for (int q = 0; q < 4; q++) acc[i][j][q] = 0.f;

    // prologue: stages 0, 1
#pragma unroll
    for (int s = 0; s < 2; s++) {
#pragma unroll
        for (int u = 0; u < 8; u++)
            cp16(sbase + s * 16384 + dstOff[u], srcB[u] + s * 32);
        cp_commit();
    }

    for (int it = 0; it < NIT; ++it) {
        cp_wait<1>();
        __syncthreads();   // all warps done with the slot we are about to fill

        if (it + 2 < NIT) {
            int st = (it + 2) % 3;
#pragma unroll
            for (int u = 0; u < 8; u++)
                cp16(sbase + st * 16384 + dstOff[u], srcB[u] + (it + 2) * 32);
        }
        cp_commit();

        const uint32_t so = (uint32_t)((it % 3) * 16384);
#pragma unroll
        for (int ks = 0; ks < 2; ks++) {
            uint32_t ah[2][4], al[2][4], bh[2][4], bl[2][4];
            ldm4(ah[0], aAd[0][0][ks] + so); ldm4(ah[1], aAd[0][1][ks] + so);
            ldm4(al[0], aAd[1][0][ks] + so); ldm4(al[1], aAd[1][1][ks] + so);
            ldm4(bh[0], bAd[0][0][ks] + so); ldm4(bh[1], bAd[0][1][ks] + so);
            ldm4(bl[0], bAd[1][0][ks] + so); ldm4(bl[1], bAd[1][1][ks] + so);
#pragma unroll
            for (int mt = 0; mt < 2; mt++) {
#pragma unroll
                for (int nt = 0; nt < 4; nt++) {
                    int lm = nt >> 1, s = nt & 1;
                    uint32_t b0h = bh[lm][s], b1h = bh[lm][2 + s];
                    uint32_t b0l = bl[lm][s], b1l = bl[lm][2 + s];
                    mma16816(acc[mt][nt], ah[mt], b0h, b1h);   // hi*hi
                    mma16816(acc[mt][nt], ah[mt], b0l, b1l);   // hi*lo
                    mma16816(acc[mt][nt], al[mt], b0h, b1h);   // lo*hi
                }
            }
        }
    }

    // epilogue
    const int g = lane >> 2, tq = lane & 3;
#pragma unroll
    for (int mt = 0; mt < 2; mt++) {
        int r = m0 + wm * 32 + mt * 16 + g;
#pragma unroll
        for (int nt = 0; nt < 4; nt++) {
            int cc = n0 + wn * 32 + nt * 8 + tq * 2;
            float2 v0 = make_float2(acc[mt][nt][0], acc[mt][nt][1]);
            float2 v1 = make_float2(acc[mt][nt][2], acc[mt][nt][3]);
            if (isPlb) {
                float2 bb = *(const float2*)(b1 + cc);
                v0.x += bb.x; v0.y += bb.y;
                v1.x += bb.x; v1.y += bb.y;
            }
            *(float2*)(Cptr + (size_t)r * ATT_ + cc)       = v0;
            *(float2*)(Cptr + (size_t)(r + 8) * ATT_ + cc) = v1;
        }
    }
}

// ---------------------------------------------------------------------------
// Fused attention v3: per block = (b, 8 n). 256 threads / 8 warps.
// Warp w owns j-pair (2*(w&3), 2*(w&3)+1), h = (w>>2) + 2*i (25 iters).
// Low registers (pnr[2][8]) -> smem-limited 4 blocks/SM, MUFU-bound.
// ---------------------------------------------------------------------------
#define NPB 8
__global__ __launch_bounds__(256, 4)
void attn_kernel(const float* __restrict__ log_vec,
                 const float* __restrict__ pos_emb,
                 const int*   __restrict__ log_mask,
                 const float* __restrict__ W2,
                 float* __restrict__ out_u) {
    extern __shared__ float sm[];
    float* plb_s    = sm;                    // 50*256 = 12800
    float* logits_s = sm + HL_ * ATT_;       // 8*64
    float* attn_s   = logits_s + NPB * 64;   // 8*64
    __shared__ int mask_s[HL_];

    const int b  = blockIdx.y;
    const int n0 = blockIdx.x * NPB;
    const int tid = threadIdx.x;
    const int lane = tid & 31, w = tid >> 5;

    // stage plb[b] (50x256) into smem
    {
        const float4* src = (const float4*)(g_plb + b * HL_ * ATT_);
        float4* dst = (float4*)plb_s;
        for (int i = tid; i < HL_ * ATT_ / 4; i += 256) dst[i] = src[i];
    }
    if (tid < HL_) mask_s[tid] = log_mask[b * HL_ + tid];

    const int pair  = w & 3;       // j-pair: rows 2*pair, 2*pair+1
    const int hbase = w >> 2;      // 0 or 1

    float pnr[2][8], w2r[8];
    #pragma unroll
    for (int j8 = 0; j8 < 8; j8++) {
        int a = lane + 32 * j8;
        w2r[j8] = W2[a];
        pnr[0][j8] = g_pn[(b * NN_ + n0 + 2 * pair)     * ATT_ + a];
        pnr[1][j8] = g_pn[(b * NN_ + n0 + 2 * pair + 1) * ATT_ + a];
    }
    __syncthreads();

    // logits: 25 h-iterations per warp
    #pragma unroll 5
    for (int i = 0; i < 25; i++) {
        const int h = hbase + 2 * i;
        float acc0 = 0.f, acc1 = 0.f;
        #pragma unroll
        for (int j8 = 0; j8 < 8; j8++) {
            float pl = plb_s[h * ATT_ + lane + 32 * j8];
            acc0 = fmaf(tanh_approx(pl + pnr[0][j8]), w2r[j8], acc0);
            acc1 = fmaf(tanh_approx(pl + pnr[1][j8]), w2r[j8], acc1);
        }
        #pragma unroll
        for (int s = 16; s; s >>= 1) {
            acc0 += __shfl_xor_sync(0xffffffffu, acc0, s);
            acc1 += __shfl_xor_sync(0xffffffffu, acc1, s);
        }
        if (lane == 0) {
            logits_s[(2 * pair)     * 64 + h] = acc0;
            logits_s[(2 * pair + 1) * 64 + h] = acc1;
        }
    }
    __syncthreads();

    // masked softmax: warp j handles row j
    {
        const int j = w;
        int h0 = lane, h1 = lane + 32;
        float v0 = -3e38f, v1 = -3e38f;
        if (h0 < HL_) v0 = (mask_s[h0] == 0) ? -1e9f : logits_s[j * 64 + h0];
        if (h1 < HL_) v1 = (mask_s[h1] == 0) ? -1e9f : logits_s[j * 64 + h1];
        float m = fmaxf(v0, v1);
        #pragma unroll
        for (int s = 16; s; s >>= 1) m = fmaxf(m, __shfl_xor_sync(0xffffffffu, m, s));
        float e0 = (h0 < HL_) ? __expf(v0 - m) : 0.f;
        float e1 = (h1 < HL_) ? __expf(v1 - m) : 0.f;
        float ssum = e0 + e1;
        #pragma unroll
        for (int s = 16; s; s >>= 1) ssum += __shfl_xor_sync(0xffffffffu, ssum, s);
        float inv = 1.f / ssum;
        if (h0 < HL_) attn_s[j * 64 + h0] = e0 * inv;
        if (h1 < HL_) attn_s[j * 64 + h1] = e1 * inv;
    }
    __syncthreads();

    // epilogue: out[b, n0+j, d] = sum_h attn[j,h] * lf[b,h,d]
    for (int d = tid; d < NEWS_; d += 256) {
        float acc[NPB];
        #pragma unroll
        for (int j = 0; j < NPB; j++) acc[j] = 0.f;
        if (d < IN_) {
            for (int h = 0; h < HL_; h++) {
                float lv = log_vec[(b * HL_ + h) * IN_ + d];
                #pragma unroll
                for (int j = 0; j < NPB; j++)
                    acc[j] = fmaf(attn_s[j * 64 + h], lv, acc[j]);
            }
        } else {
            int dp = d - IN_;
            for (int h = 0; h < HL_; h++) {
                float lv = pos_emb[(1 + h) * POS_ + dp];
                #pragma unroll
                for (int j = 0; j < NPB; j++)
                    acc[j] = fmaf(attn_s[j * 64 + h], lv, acc[j]);
            }
        }
        #pragma unroll
        for (int j = 0; j < NPB; j++)
            out_u[(b * NN_ + n0 + j) * NEWS_ + d] = acc[j];
    }
}

// ---------------------------------------------------------------------------
extern "C" void kernel_launch(void* const* d_in, const int* in_sizes, int n_in,
                              void* d_out, int out_size) {
    const float* log_vec  = (const float*)d_in[0];   // (64,50,384)
    const int*   log_mask = (const int*)  d_in[1];   // (64,50)
    const float* news_vec = (const float*)d_in[2];   // (64,64,384)
    const float* pos_emb  = (const float*)d_in[3];   // (100,64)
    const float* W1       = (const float*)d_in[4];   // (256,896)
    const float* b1       = (const float*)d_in[5];   // (256)
    const float* W2       = (const float*)d_in[6];   // (1,256)
    // d_in[7] = b2: cancels in softmax, unused.

    float* out    = (float*)d_out;
    float* out_u  = out;                         // user_log_vecs: 4096*448
    float* out_nf = out + B_ * NN_ * NEWS_;      // nf:            4096*448

    // 1) convert operands to bf16 hi/lo + emit nf output (flat, full lanes)
    prep_kernel<<<3400, 256>>>(log_vec, news_vec, pos_emb, W1, out_nf);

    // 2) both projection GEMMs on tensor cores (one launch)
    gemm_tc_kernel<<<dim3(ATT_ / 64, 64 + 50), 128>>>(b1);

    // 3) fused tanh-attention + softmax + weighted sum
    {
        size_t smem = (size_t)(HL_ * ATT_ + NPB * 64 * 2) * sizeof(float); // 55296
        cudaFuncSetAttribute(attn_kernel, cudaFuncAttributeMaxDynamicSharedMemorySize,
                             (int)smem);
        attn_kernel<<<dim3(NN_ / NPB, B_), 256, smem>>>(log_vec, pos_emb,
                                                        log_mask, W2, out_u);
    }
}